// round 9
// baseline (speedup 1.0000x reference)
#include <cuda_runtime.h>
#include <cuda_bf16.h>
#include <stdint.h>

#define NN 96
#define DD 64
#define CC 30
#define PREP_BLOCKS 48                     // 36 mat + 12 label; then 2 anchors/block
#define TOTAL_BLOCKS (PREP_BLOCKS + NN*NN) // 9264

// Scratch (__device__ globals; no allocation allowed)
__device__ float    g_mat[NN * NN];
__device__ unsigned g_smask[NN * 3];
__device__ unsigned g_dmask[NN * 3];
__device__ unsigned g_cmask[NN * NN * 4];  // 96-bit mask per (i,p), stride 4 words
__device__ unsigned g_count;               // prep-internal barrier (monotonic; +48/launch)
__device__ unsigned g_done;                // cmask-ready flag (reset at kernel end)
__device__ unsigned g_fin;                 // completion counter (reset at kernel end)

// ---------------------------------------------------------------------------
// ONE kernel, 9264 blocks x 256 threads.
//  blocks 0..47   : prep (mat / labels -> barrier -> eps -> cmask), then
//                   publish g_done.
//  blocks 48..9263: writer, one FULL slab (i,j) each (proven 6.9 TB/s shape),
//                   ordered j DESCENDING so early blocks are zero-dominated:
//                     1) write zero prefix (k <= j)   [no dependency]
//                     2) wait g_done >= 48            [hidden under 1)]
//                     3) stage AND-mask in smem, write data suffix (k > j)
//  tail (all)     : last finisher resets g_done/g_fin -> graph-replay-safe.
// ---------------------------------------------------------------------------
__global__ __launch_bounds__(256) void mega(const float* __restrict__ logits,
                                            const float* __restrict__ labels,
                                            float4* __restrict__ out) {
    const int tid = threadIdx.x;
    const int bid = blockIdx.x;

    if (bid >= PREP_BLOCKS) {
        // ========================= writer =========================
        __shared__ unsigned sw[NN * 3];
        const int zid = bid - PREP_BLOCKS;       // 0..9215
        const int q   = zid / NN;                // 0..95
        const int i   = zid - q * NN;            // anchor
        const int j   = NN - 1 - q;              // j descending with bid
        float4* o = out + ((size_t)i * NN + j) * 2304;
        const int len1 = (j + 1) * 24;           // zero prefix (k <= j)

        const float4 z4 = make_float4(0.f, 0.f, 0.f, 0.f);
        for (int pos = tid; pos < len1; pos += 256)
            __stcs(o + pos, z4);

        if (j < NN - 1) {
            if (tid == 0) {
                while (*(volatile unsigned*)&g_done < PREP_BLOCKS) { }
                __threadfence();                 // acquire cmask
            }
            __syncthreads();

            const int r2w = (i * NN + j) << 2;
            for (int t = tid; t < NN * 3; t += 256) {
                int k  = t / 3;
                int wd = t - k * 3;
                sw[t] = g_cmask[r2w + wd] & g_cmask[((i * NN + k) << 2) + wd];
            }
            __syncthreads();

            const unsigned ONEF = 0x3f800000u;
            for (int pos = len1 + tid; pos < 2304; pos += 256) {
                int k = pos / 24;
                int r = pos - k * 24;
                unsigned w = sw[k * 3 + (r >> 3)];
                unsigned b = w >> ((r & 7) * 4);
                float4 v;
                v.x = __uint_as_float(ONEF & (0u - (b & 1u)));
                v.y = __uint_as_float(ONEF & (0u - ((b >> 1) & 1u)));
                v.z = __uint_as_float(ONEF & (0u - ((b >> 2) & 1u)));
                v.w = __uint_as_float(ONEF & (0u - ((b >> 3) & 1u)));
                __stcs(o + pos, v);
            }
        }
    } else {
        // ========================= prep (0..47) =========================
        __shared__ float    sx[NN * 65];
        __shared__ float    rn[NN];
        __shared__ float    s_rnum[NN], s_rq[NN];
        __shared__ float    s_eps;
        __shared__ float    srow[NN];
        __shared__ unsigned sm[3], dm[3];

        const int warp = tid >> 5, lane = tid & 31;

        if (bid < 36) {
            // ---- mat: one output per thread ----
            #pragma unroll
            for (int it = 0; it < 24; it++) {         // 6144 = 24*256
                int t = it * 256 + tid;
                sx[(t >> 6) * 65 + (t & 63)] = logits[t];
            }
            __syncthreads();
            if (tid < NN) {                           // norms (bit-identical order)
                float s = 0.f;
                #pragma unroll
                for (int d = 0; d < DD; d++) { float v = sx[tid * 65 + d]; s += v * v; }
                rn[tid] = rsqrtf(s);
            }
            __syncthreads();
            const int outp = bid * 256 + tid;         // 0..9215
            const int r = outp / NN;
            const int c = outp - r * NN;
            float acc = 0.f;
            #pragma unroll
            for (int d = 0; d < DD; d++) acc += sx[r * 65 + d] * sx[c * 65 + d];
            g_mat[outp] = -acc * rn[r] * rn[c];
        } else {
            // ---- labels: one warp per row, 8 rows per block ----
            #pragma unroll
            for (int it = 0; it < 12; it++) {         // 2880 = 96*30
                int t = it * 256 + tid;
                if (t < NN * CC) sx[t] = labels[t];
            }
            __syncthreads();
            const int i = (bid - 36) * 8 + warp;      // row 0..95
            #pragma unroll
            for (int wd = 0; wd < 3; wd++) {
                int j = wd * 32 + lane;
                float acc = 0.f;
                #pragma unroll
                for (int cc = 0; cc < CC; cc++) acc += sx[i * CC + cc] * sx[j * CC + cc];
                bool same_raw = acc > 0.f;
                unsigned sb = __ballot_sync(0xffffffffu, same_raw && (j != i));
                unsigned db = __ballot_sync(0xffffffffu, !same_raw);
                if (lane == 0) {
                    g_smask[i * 3 + wd] = sb;
                    g_dmask[i * 3 + wd] = db;
                }
            }
        }

        // ---- barrier among the 48 prep blocks (wave 1 -> co-resident) ----
        __threadfence();                              // publish mat / masks
        __syncthreads();
        if (tid == 0) {
            unsigned prev   = atomicAdd(&g_count, 1u);
            unsigned target = (prev / PREP_BLOCKS + 1u) * PREP_BLOCKS;
            while (*(volatile unsigned*)&g_count < target) { }
            __threadfence();                          // acquire
        }
        __syncthreads();

        // ---- epsilon: identical math/order in every block -> deterministic ----
        for (int i = warp; i < NN; i += 8) {
            float S = 0.f, ds = 0.f, ms = 0.f, md = 0.f;
            #pragma unroll
            for (int jj = 0; jj < 3; jj++) {
                float mv = g_mat[i * NN + jj * 32 + lane];
                if ((g_smask[i * 3 + jj] >> lane) & 1u) { S += 1.f; ms += mv; }
                if ((g_dmask[i * 3 + jj] >> lane) & 1u) { ds += 1.f; md += mv; }
            }
            #pragma unroll
            for (int o = 16; o; o >>= 1) {
                S  += __shfl_xor_sync(0xffffffffu, S,  o);
                ds += __shfl_xor_sync(0xffffffffu, ds, o);
                ms += __shfl_xor_sync(0xffffffffu, ms, o);
                md += __shfl_xor_sync(0xffffffffu, md, o);
            }
            if (lane == 0) {
                s_rnum[i] = (S - 1.f) * (S * md - ms * ds);
                s_rq[i]   = 0.5f * S * (S - 1.f) * ds;
            }
        }
        __syncthreads();
        if (tid == 0) {   // serial reduce: identical order every block
            float num = 0.f, q = 0.f;
            for (int i = 0; i < NN; i++) { num += s_rnum[i]; q += s_rq[i]; }
            float mean_delta = num / fmaxf(2.f * q, 1.f);
            s_eps = fmaxf(mean_delta * 0.5f, 0.f);   // relu(mean_delta / K_DELTA)
        }
        __syncthreads();
        const float eps = s_eps;

        // ---- cmask for 2 anchors per block ----
        #pragma unroll
        for (int a0 = 0; a0 < 2; a0++) {
            const int ianc = bid * 2 + a0;
            if (tid < NN) srow[tid] = g_mat[ianc * NN + tid];
            if (tid >= NN && tid < NN + 3) {
                sm[tid - NN] = g_smask[ianc * 3 + (tid - NN)];
                dm[tid - NN] = g_dmask[ianc * 3 + (tid - NN)];
            }
            __syncthreads();
            for (int p = warp; p < NN; p += 8) {
                unsigned sp = (sm[p >> 5] >> (p & 31)) & 1u;
                float matp = srow[p];
                #pragma unroll
                for (int wd = 0; wd < 3; wd++) {
                    float m = srow[wd * 32 + lane] - matp;
                    bool cc = sp && (((dm[wd] >> lane) & 1u) != 0u) && (m > 0.f) && (m <= eps);
                    unsigned b = __ballot_sync(0xffffffffu, cc);
                    if (lane == 0) g_cmask[(ianc * NN + p) * 4 + wd] = b;
                }
            }
            __syncthreads();
        }

        // ---- publish cmask ready ----
        __threadfence();
        __syncthreads();
        if (tid == 0) atomicAdd(&g_done, 1u);
    }

    // ========================= tail: replay-safe reset =========================
    __syncthreads();
    if (tid == 0) {
        __threadfence();
        unsigned prev = atomicAdd(&g_fin, 1u);
        if (prev == (unsigned)TOTAL_BLOCKS - 1u) {
            // Last block to finish: every other block has already passed its
            // wait (waits precede the fin-increment). Reset for next replay.
            g_done = 0u;
            g_fin  = 0u;
            __threadfence();
        }
    }
}

// ---------------------------------------------------------------------------
extern "C" void kernel_launch(void* const* d_in, const int* in_sizes, int n_in,
                              void* d_out, int out_size) {
    const float* logits = (const float*)d_in[0];   // [96,64]
    const float* labels = (const float*)d_in[1];   // [96,30]

    mega<<<TOTAL_BLOCKS, 256>>>(logits, labels, (float4*)d_out);
}

// round 10
// speedup vs baseline: 1.1143x; 1.1143x over previous
#include <cuda_runtime.h>
#include <cuda_bf16.h>
#include <stdint.h>

#define NN 96
#define DD 64
#define CC 30
#define PREP_BLOCKS 48   // 36 mat + 12 label; then 2 anchors/block for cmask

// Scratch (__device__ globals; no allocation allowed)
__device__ float    g_mat[NN * NN];
__device__ unsigned g_smask[NN * 3];
__device__ unsigned g_dmask[NN * 3];
__device__ unsigned g_cmask[NN * NN * 4];  // 96-bit mask per (i,p), stride 4 words
__device__ unsigned g_count;               // prep barrier (monotonic; +48 per launch)

// ---------------------------------------------------------------------------
// prep: 48 blocks x 256. Triggers the dependent writer launch AT ENTRY so the
// writer's zero stream overlaps all of prep. Math verbatim from the passing
// R7 kernel (bit-identical mask).
// ---------------------------------------------------------------------------
__global__ __launch_bounds__(256) void prep(const float* __restrict__ logits,
                                            const float* __restrict__ labels) {
#if __CUDA_ARCH__ >= 900
    cudaTriggerProgrammaticLaunchCompletion();   // let the writer start NOW
#endif
    __shared__ float    sx[NN * 65];
    __shared__ float    rn[NN];
    __shared__ float    s_rnum[NN], s_rq[NN];
    __shared__ float    s_eps;
    __shared__ float    srow[NN];
    __shared__ unsigned sm[3], dm[3];

    const int tid  = threadIdx.x;
    const int bid  = blockIdx.x;
    const int warp = tid >> 5, lane = tid & 31;

    if (bid < 36) {
        // ---- mat: one output per thread ----
        #pragma unroll
        for (int it = 0; it < 24; it++) {             // 6144 = 24*256
            int t = it * 256 + tid;
            sx[(t >> 6) * 65 + (t & 63)] = logits[t];
        }
        __syncthreads();
        if (tid < NN) {                               // norms (bit-identical order)
            float s = 0.f;
            #pragma unroll
            for (int d = 0; d < DD; d++) { float v = sx[tid * 65 + d]; s += v * v; }
            rn[tid] = rsqrtf(s);
        }
        __syncthreads();
        const int outp = bid * 256 + tid;             // 0..9215
        const int r = outp / NN;
        const int c = outp - r * NN;
        float acc = 0.f;
        #pragma unroll
        for (int d = 0; d < DD; d++) acc += sx[r * 65 + d] * sx[c * 65 + d];
        g_mat[outp] = -acc * rn[r] * rn[c];
    } else {
        // ---- labels: one warp per row, 8 rows per block ----
        #pragma unroll
        for (int it = 0; it < 12; it++) {             // 2880 = 96*30
            int t = it * 256 + tid;
            if (t < NN * CC) sx[t] = labels[t];
        }
        __syncthreads();
        const int i = (bid - 36) * 8 + warp;          // row 0..95
        #pragma unroll
        for (int wd = 0; wd < 3; wd++) {
            int j = wd * 32 + lane;
            float acc = 0.f;
            #pragma unroll
            for (int cc = 0; cc < CC; cc++) acc += sx[i * CC + cc] * sx[j * CC + cc];
            bool same_raw = acc > 0.f;
            unsigned sb = __ballot_sync(0xffffffffu, same_raw && (j != i));
            unsigned db = __ballot_sync(0xffffffffu, !same_raw);
            if (lane == 0) {
                g_smask[i * 3 + wd] = sb;
                g_dmask[i * 3 + wd] = db;
            }
        }
    }

    // ---- barrier among the 48 prep blocks (all co-resident) ----
    __threadfence();                                  // publish mat / masks
    __syncthreads();
    if (tid == 0) {
        unsigned prev   = atomicAdd(&g_count, 1u);
        unsigned target = (prev / PREP_BLOCKS + 1u) * PREP_BLOCKS;
        while (*(volatile unsigned*)&g_count < target) { }
        __threadfence();                              // acquire
    }
    __syncthreads();

    // ---- epsilon: identical math/order in every block -> deterministic ----
    for (int i = warp; i < NN; i += 8) {
        float S = 0.f, ds = 0.f, ms = 0.f, md = 0.f;
        #pragma unroll
        for (int jj = 0; jj < 3; jj++) {
            float mv = g_mat[i * NN + jj * 32 + lane];
            if ((g_smask[i * 3 + jj] >> lane) & 1u) { S += 1.f; ms += mv; }
            if ((g_dmask[i * 3 + jj] >> lane) & 1u) { ds += 1.f; md += mv; }
        }
        #pragma unroll
        for (int o = 16; o; o >>= 1) {
            S  += __shfl_xor_sync(0xffffffffu, S,  o);
            ds += __shfl_xor_sync(0xffffffffu, ds, o);
            ms += __shfl_xor_sync(0xffffffffu, ms, o);
            md += __shfl_xor_sync(0xffffffffu, md, o);
        }
        if (lane == 0) {
            s_rnum[i] = (S - 1.f) * (S * md - ms * ds);
            s_rq[i]   = 0.5f * S * (S - 1.f) * ds;
        }
    }
    __syncthreads();
    if (tid == 0) {   // serial reduce: identical order every block
        float num = 0.f, q = 0.f;
        for (int i = 0; i < NN; i++) { num += s_rnum[i]; q += s_rq[i]; }
        float mean_delta = num / fmaxf(2.f * q, 1.f);
        s_eps = fmaxf(mean_delta * 0.5f, 0.f);   // relu(mean_delta / K_DELTA)
    }
    __syncthreads();
    const float eps = s_eps;

    // ---- cmask for 2 anchors per block ----
    #pragma unroll
    for (int a0 = 0; a0 < 2; a0++) {
        const int ianc = bid * 2 + a0;
        if (tid < NN) srow[tid] = g_mat[ianc * NN + tid];
        if (tid >= NN && tid < NN + 3) {
            sm[tid - NN] = g_smask[ianc * 3 + (tid - NN)];
            dm[tid - NN] = g_dmask[ianc * 3 + (tid - NN)];
        }
        __syncthreads();
        for (int p = warp; p < NN; p += 8) {
            unsigned sp = (sm[p >> 5] >> (p & 31)) & 1u;
            float matp = srow[p];
            #pragma unroll
            for (int wd = 0; wd < 3; wd++) {
                float m = srow[wd * 32 + lane] - matp;
                bool cc = sp && (((dm[wd] >> lane) & 1u) != 0u) && (m > 0.f) && (m <= eps);
                unsigned b = __ballot_sync(0xffffffffu, cc);
                if (lane == 0) g_cmask[(ianc * NN + p) * 4 + wd] = b;
            }
        }
        __syncthreads();
    }
}

// ---------------------------------------------------------------------------
// writer: 9216 blocks x 256, PDL secondary. One FULL slab per block (the
// proven 6.9 TB/s shape), j DESCENDING so wave-1 blocks are zero-dominated:
//   1) zero prefix (k <= j)                [no dependency on prep]
//   2) cudaGridDependencySynchronize()     [waits prep; hidden under 1)]
//   3) stage AND-mask in smem, write data suffix (k > j)
// ---------------------------------------------------------------------------
__global__ __launch_bounds__(256) void writer(float4* __restrict__ out) {
    __shared__ unsigned sw[NN * 3];
    const int tid = threadIdx.x;
    const int bid = blockIdx.x;              // 0..9215
    const int q   = bid / NN;                // 0..95
    const int i   = bid - q * NN;            // anchor
    const int j   = NN - 1 - q;              // j descending with bid
    float4* o = out + ((size_t)i * NN + j) * 2304;
    const int len1 = (j + 1) * 24;           // zero prefix (k <= j)

    const float4 z4 = make_float4(0.f, 0.f, 0.f, 0.f);
    for (int pos = tid; pos < len1; pos += 256)
        __stcs(o + pos, z4);

    if (j == NN - 1) return;                 // fully-zero slab, no dependency

#if __CUDA_ARCH__ >= 900
    cudaGridDependencySynchronize();         // prep complete + visible
#endif

    const int r2w    = (i * NN + j) << 2;
    const int ibase4 = (i * NN) << 2;
    for (int t = tid; t < NN * 3; t += 256) {
        int k  = t / 3;
        int wd = t - k * 3;
        sw[t] = g_cmask[r2w + wd] & g_cmask[ibase4 + (k << 2) + wd];
    }
    __syncthreads();

    const unsigned ONEF = 0x3f800000u;
    for (int pos = len1 + tid; pos < 2304; pos += 256) {
        int k = pos / 24;
        int r = pos - k * 24;
        unsigned w = sw[k * 3 + (r >> 3)];
        unsigned b = w >> ((r & 7) * 4);
        float4 v;
        v.x = __uint_as_float(ONEF & (0u - (b & 1u)));
        v.y = __uint_as_float(ONEF & (0u - ((b >> 1) & 1u)));
        v.z = __uint_as_float(ONEF & (0u - ((b >> 2) & 1u)));
        v.w = __uint_as_float(ONEF & (0u - ((b >> 3) & 1u)));
        __stcs(o + pos, v);
    }
}

// ---------------------------------------------------------------------------
extern "C" void kernel_launch(void* const* d_in, const int* in_sizes, int n_in,
                              void* d_out, int out_size) {
    const float* logits = (const float*)d_in[0];   // [96,64]
    const float* labels = (const float*)d_in[1];   // [96,30]

    prep<<<PREP_BLOCKS, 256>>>(logits, labels);

    // Writer as PDL secondary: may begin while prep is still running; its
    // cmask reads are guarded by cudaGridDependencySynchronize().
    cudaLaunchConfig_t cfg = {};
    cfg.gridDim  = dim3(NN * NN);
    cfg.blockDim = dim3(256);
    cfg.dynamicSmemBytes = 0;
    cfg.stream = 0;
    cudaLaunchAttribute attr[1];
    attr[0].id = cudaLaunchAttributeProgrammaticStreamSerialization;
    attr[0].val.programmaticStreamSerializationAllowed = 1;
    cfg.attrs = attr;
    cfg.numAttrs = 1;
    cudaLaunchKernelEx(&cfg, writer, (float4*)d_out);
}